// round 5
// baseline (speedup 1.0000x reference)
#include <cuda_runtime.h>
#include <math.h>
#include <stdint.h>

#define R_N 1000
#define K_N 80
#define NCLS_P1 81
#define IMG_W_F 1333.0f
#define IMG_H_F 800.0f
#define CPC 100
#define OUT_COLS 87
#define TB 512

typedef unsigned long long u64;
typedef unsigned int u32;

__device__ float g_psum[K_N];
__device__ float g_pmax[K_N];
__device__ u32 g_ord[K_N * CPC];
__device__ int g_prop[K_N * CPC];
__device__ int g_bar1 = 0;
__device__ int g_bar2 = 0;

__device__ __forceinline__ u32 ord32(float f) {
    u32 u = __float_as_uint(f);
    return (u & 0x80000000u) ? ~u : (u | 0x80000000u);
}

// low-32 tie-break for flat index i = c*100+k: strictly decreasing in i,
// so (ord desc, tb desc) == (ord desc, c asc, k asc) == flat top_k order.
__device__ __forceinline__ u32 tb_of(int i) {
    int c = i / CPC;
    int k = i - c * CPC;
    return (u32)(((K_N - 1 - c) << 7) | (CPC - 1 - k));
}

// dynamic smem byte offsets -- phase 3 layout
#define OFF_ALLBOX   0        // float4[1000]  16000
#define OFF_ALLSCORE 16384    // float[1000]    4000
#define OFF_CSCORE   20480    // float[1024]
#define OFF_CIDX     24576    // int[1024]
#define OFF_SSCORE   28672    // float[1024]
#define OFF_SIDX     32768    // int[1024]
#define OFF_SBX      36864    // float4[1024]  16384
#define OFF_SAREA    53248    // float[1024]
#define DYN_SMEM     57344
// phase 4 layout (block 0 only, reuses the same region)
#define OFF_ORDSH    0        // u32[8000]  32000
#define OFF_HIST     32768    // u32[256]
#define OFF_SURV     36864    // u64[128]
#define OFF_WIN      40960    // u64[128]

__global__ void __launch_bounds__(TB) fused_kernel(const float* __restrict__ boxes,
                                                   const float* __restrict__ scores,
                                                   float* __restrict__ out) {
    extern __shared__ char smraw[];
    float4* allbox   = (float4*)(smraw + OFF_ALLBOX);
    float*  allscore = (float*)(smraw + OFF_ALLSCORE);
    float*  cscore   = (float*)(smraw + OFF_CSCORE);
    int*    cidx     = (int*)(smraw + OFF_CIDX);
    float*  sscore   = (float*)(smraw + OFF_SSCORE);
    int*    sidx     = (int*)(smraw + OFF_SIDX);
    float4* sbx      = (float4*)(smraw + OFF_SBX);
    float*  sarea    = (float*)(smraw + OFF_SAREA);

    __shared__ float wsum[TB / 32], wmax[TB / 32];
    __shared__ float rsum[128], rmax[128];
    __shared__ int klist[CPC];
    __shared__ int s_cnt, s_nk, s_chosen, s_need, s_scount;

    int t = threadIdx.x;
    int b = blockIdx.x;       // class id

    // ---- Phase 1: partial mean/max over this block's 1000-elem fg slice ----
    {
        float psum = 0.f, pmax = -INFINITY;
        for (int j = t; j < 1000; j += TB) {
            int idx = b * 1000 + j;
            int r = idx / K_N;
            int c = idx - r * K_N;
            float v = __ldg(scores + r * NCLS_P1 + c);
            psum += v;
            pmax = fmaxf(pmax, v);
        }
        #pragma unroll
        for (int o = 16; o; o >>= 1) {
            psum += __shfl_xor_sync(0xffffffffu, psum, o);
            pmax = fmaxf(pmax, __shfl_xor_sync(0xffffffffu, pmax, o));
        }
        if ((t & 31) == 0) { wsum[t >> 5] = psum; wmax[t >> 5] = pmax; }
    }
    __syncthreads();
    if (t == 0) {
        float s = 0.f, m = -INFINITY;
        #pragma unroll
        for (int i = 0; i < TB / 32; i++) { s += wsum[i]; m = fmaxf(m, wmax[i]); }
        g_psum[b] = s; g_pmax[b] = m;
        __threadfence();
        atomicAdd(&g_bar1, 1);
    }

    // ---- Prefetch this class's column (overlaps the grid-barrier wait) ----
    for (int r = t; r < R_N; r += TB) {
        allscore[r] = __ldg(scores + r * NCLS_P1 + b);
        allbox[r]   = __ldg((const float4*)boxes + r * K_N + b);
    }
    if (t == 0) {
        while (*(volatile int*)&g_bar1 < K_N) { }
        __threadfence();
        s_cnt = 0;
    }
    __syncthreads();

    // ---- Phase 2: fold 80 partials (identical tree in every block) ----
    if (t < 128) {
        rsum[t] = (t < K_N) ? g_psum[t] : 0.f;
        rmax[t] = (t < K_N) ? g_pmax[t] : -INFINITY;
    }
    __syncthreads();
    #pragma unroll
    for (int s = 64; s > 0; s >>= 1) {
        if (t < s) { rsum[t] += rsum[t + s]; rmax[t] = fmaxf(rmax[t], rmax[t + s]); }
        __syncthreads();
    }
    float th = fminf(0.05f, 0.5f * (rsum[0] / (float)(R_N * K_N) + rmax[0]));

    // ---- Phase 3a: compact valid (order arbitrary; fixed by rank sort) ----
    for (int r = t; r < R_N; r += TB) {
        float s = allscore[r];
        if (s > th) {
            int p = atomicAdd(&s_cnt, 1);
            cscore[p] = s;
            cidx[p] = r;
        }
    }
    __syncthreads();
    int V = s_cnt;

    // ---- Phase 3b: rank-counting sort (score desc, idx asc) + gather boxes ----
    for (int i = t; i < V; i += TB) {
        float si = cscore[i];
        int   ii = cidx[i];
        int rank = 0;
        for (int j = 0; j < V; j++) {
            float sj = cscore[j];
            rank += (sj > si) || (sj == si && cidx[j] < ii);
        }
        float4 bx = allbox[ii];
        float x1 = fminf(fmaxf(bx.x, 0.f), IMG_W_F);
        float y1 = fminf(fmaxf(bx.y, 0.f), IMG_H_F);
        float x2 = fminf(fmaxf(bx.z, 0.f), IMG_W_F);
        float y2 = fminf(fmaxf(bx.w, 0.f), IMG_H_F);
        sscore[rank] = si;
        sidx[rank]   = ii;
        sbx[rank]    = make_float4(x1, y1, x2, y2);
        sarea[rank]  = fmaxf(x2 - x1, 0.f) * fmaxf(y2 - y1, 0.f);
    }
    __syncthreads();

    // ---- Phase 3c: warp-register greedy NMS (warp 0, no block barriers) ----
    if (t < 32) {
        int lane = t;
        u64 removed = 0;                       // lane w owns bits [64w, 64w+64)
        int nk = 0;
        for (int i = 0; i < V; i++) {
            u64 wv = __shfl_sync(0xffffffffu, removed, i >> 6);
            if (!((wv >> (i & 63)) & 1ull)) {
                if (lane == 0) klist[nk] = i;
                nk++;
                if (nk >= CPC) break;
                float4 bi = sbx[i];
                float  ai = sarea[i];
                for (int jb = i + 1; jb < V; jb += 32) {
                    int j = jb + lane;
                    bool sup = false;
                    if (j < V) {
                        float4 bj = sbx[j];
                        float xx1 = fmaxf(bi.x, bj.x);
                        float yy1 = fmaxf(bi.y, bj.y);
                        float xx2 = fminf(bi.z, bj.z);
                        float yy2 = fminf(bi.w, bj.w);
                        float inter = fmaxf(xx2 - xx1, 0.f) * fmaxf(yy2 - yy1, 0.f);
                        float uni = fmaxf(ai + sarea[j] - inter, 1e-9f);
                        sup = inter > 0.5f * uni;
                    }
                    u32 bm = __ballot_sync(0xffffffffu, sup);
                    int w0 = jb >> 6, off0 = jb & 63;
                    if (lane == w0)     removed |= ((u64)bm) << off0;
                    if (lane == w0 + 1 && off0) removed |= ((u64)bm) >> (64 - off0);
                }
            }
        }
        if (lane == 0) s_nk = nk;
    }
    __syncthreads();

    // ---- Phase 3d: emit top-100 kept (sorted) ----
    {
        int nk = s_nk;
        int base = b * CPC;
        if (t < CPC) {
            if (t < nk) {
                int i = klist[t];
                g_ord[base + t]  = ord32(sscore[i]);
                g_prop[base + t] = sidx[i];
            } else {
                g_ord[base + t]  = 0u;
                g_prop[base + t] = 0;
            }
        }
    }
    __syncthreads();

    // ---- grid barrier 2; only block 0 continues ----
    if (t == 0) { __threadfence(); atomicAdd(&g_bar2, 1); }
    if (b != 0) return;
    if (t == 0) {
        while (*(volatile int*)&g_bar2 < K_N) { }
        __threadfence();
        s_scount = 0;
    }
    __syncthreads();

    // ---- Phase 4: exact top-100 via 8-pass u64 byte-radix select ----
    u32* ordsh = (u32*)(smraw + OFF_ORDSH);
    u32* hist  = (u32*)(smraw + OFF_HIST);
    u64* surv  = (u64*)(smraw + OFF_SURV);
    u64* win   = (u64*)(smraw + OFF_WIN);

    for (int i = t; i < K_N * CPC; i += TB) ordsh[i] = g_ord[i];
    __syncthreads();

    u32 prefOrd = 0, ordMask = 0;
    u32 prefTb = 0,  tbMask = 0;
    int need = CPC;
    #pragma unroll
    for (int pass = 0; pass < 8; pass++) {
        bool ordPass = pass < 4;
        int shift = ordPass ? 8 * (3 - pass) : 8 * (7 - pass);
        for (int v = t; v < 256; v += TB) hist[v] = 0;
        __syncthreads();
        for (int i = t; i < K_N * CPC; i += TB) {
            u32 o = ordsh[i];
            u32 tb = tb_of(i);
            if (((o ^ prefOrd) & ordMask) == 0 && ((tb ^ prefTb) & tbMask) == 0) {
                u32 byte = ((ordPass ? o : tb) >> shift) & 255u;
                atomicAdd(&hist[byte], 1u);
            }
        }
        __syncthreads();
        if (t == 0) {
            int acc = 0, chosen = 0, nd = need;
            for (int v = 255; v >= 0; v--) {
                int h = (int)hist[v];
                if (acc + h >= nd) { chosen = v; nd = nd - acc; break; }
                acc += h;
            }
            s_chosen = chosen; s_need = nd;
        }
        __syncthreads();
        u32 ch = (u32)s_chosen;
        need = s_need;
        if (ordPass) { prefOrd |= ch << shift; ordMask |= 255u << shift; }
        else         { prefTb  |= ch << shift; tbMask  |= 255u << shift; }
        __syncthreads();
    }
    u64 T64 = ((u64)prefOrd << 32) | prefTb;   // exact 100th-largest key

    // gather exactly the 100 keys >= T64 (keys are unique)
    for (int i = t; i < K_N * CPC; i += TB) {
        u64 key = ((u64)ordsh[i] << 32) | tb_of(i);
        if (key >= T64) {
            int p = atomicAdd(&s_scount, 1);
            surv[p] = key;
        }
    }
    __syncthreads();
    int S = s_scount;   // == 100

    if (t < S) {
        u64 ki = surv[t];
        int r = 0;
        for (int j = 0; j < S; j++) r += (surv[j] > ki);
        win[r] = ki;
    }
    __syncthreads();

    // ---- Output: [100, 87] = box(4) | score | class | full_scores(81) ----
    for (int e = t; e < CPC * OUT_COLS; e += TB) {
        int row = e / OUT_COLS;
        int col = e - row * OUT_COLS;
        u64 key = win[row];
        u32 o = (u32)(key >> 32);
        float val = 0.f;
        if (o != 0u) {
            u32 low = (u32)key;
            int c = (K_N - 1) - (int)((low >> 7) & 127u);
            int k = (CPC - 1) - (int)(low & 127u);
            int prop = g_prop[c * CPC + k];
            if (col < 4) {
                float bv = __ldg(boxes + prop * (K_N * 4) + c * 4 + col);
                float lim = (col & 1) ? IMG_H_F : IMG_W_F;
                val = fminf(fmaxf(bv, 0.f), lim);
            } else if (col == 4) {
                val = __uint_as_float(o & 0x7FFFFFFFu);
            } else if (col == 5) {
                val = (float)c;
            } else {
                val = __ldg(scores + prop * NCLS_P1 + (col - 6));
            }
        }
        out[e] = val;
    }
    __syncthreads();
    if (t == 0) { g_bar1 = 0; g_bar2 = 0; }   // reset for next graph replay
}

// ---------------------------------------------------------------------------
extern "C" void kernel_launch(void* const* d_in, const int* in_sizes, int n_in,
                              void* d_out, int out_size) {
    const float* boxes  = (const float*)d_in[0];
    const float* scores = (const float*)d_in[1];
    if (in_sizes[0] != R_N * K_N * 4) {
        boxes  = (const float*)d_in[1];
        scores = (const float*)d_in[0];
    }
    cudaFuncSetAttribute(fused_kernel, cudaFuncAttributeMaxDynamicSharedMemorySize, DYN_SMEM);
    fused_kernel<<<K_N, TB, DYN_SMEM>>>(boxes, scores, (float*)d_out);
}

// round 6
// speedup vs baseline: 1.5100x; 1.5100x over previous
#include <cuda_runtime.h>
#include <math.h>
#include <stdint.h>

#define R_N 1000
#define K_N 80
#define NCLS_P1 81
#define IMG_W_F 1333.0f
#define IMG_H_F 800.0f
#define CPC 100
#define OUT_COLS 87
#define TB 512

typedef unsigned long long u64;
typedef unsigned int u32;

__device__ float g_psum[K_N];
__device__ float g_pmax[K_N];
__device__ u32 g_ord[K_N * CPC];
__device__ int g_prop[K_N * CPC];
__device__ int g_bar1 = 0;
__device__ int g_bar2 = 0;

__device__ __forceinline__ u32 ord32(float f) {
    u32 u = __float_as_uint(f);
    return (u & 0x80000000u) ? ~u : (u | 0x80000000u);
}

// low-32 tie-break for flat index i = c*100+k: strictly decreasing in i,
// so (ord desc, tb desc) == flat top_k order (smaller c, then smaller k).
__device__ __forceinline__ u32 tb_of(int i) {
    int c = i / CPC;
    int k = i - c * CPC;
    return (u32)(((K_N - 1 - c) << 7) | (CPC - 1 - k));
}

// ---- dynamic smem offsets: phase-3 layout ----
#define OFF_ALLSCORE 0        // float[1000]
#define OFF_CSCORE   4096     // float[1024]
#define OFF_CIDX     8192     // int[1024]
#define OFF_SSCORE   12288    // float[1024]
#define OFF_SIDX     16384    // int[1024]
#define OFF_SBX      20480    // float4[1024]
#define OFF_SAREA    36864    // float[1024]
#define DYN_SMEM     40960
// ---- phase-4 layout (block 0 reuses the region) ----
#define OFF_ORDSH    0        // u32[8000]
#define OFF_HIST     32768    // u32[256]
#define OFF_SURV     34816    // u64[128]
#define OFF_WIN      35840    // u64[128]

__global__ void __launch_bounds__(TB) fused_kernel(const float* __restrict__ boxes,
                                                   const float* __restrict__ scores,
                                                   float* __restrict__ out) {
    extern __shared__ char smraw[];
    float*  allscore = (float*)(smraw + OFF_ALLSCORE);
    float*  cscore   = (float*)(smraw + OFF_CSCORE);
    int*    cidx     = (int*)(smraw + OFF_CIDX);
    float*  sscore   = (float*)(smraw + OFF_SSCORE);
    int*    sidx     = (int*)(smraw + OFF_SIDX);
    float4* sbx      = (float4*)(smraw + OFF_SBX);
    float*  sarea    = (float*)(smraw + OFF_SAREA);

    __shared__ float wsum[TB / 32], wmax[TB / 32];
    __shared__ float rsum[128], rmax[128];
    __shared__ int klist[CPC];
    __shared__ int s_cnt, s_nk, s_chosen, s_need, s_scount;

    int t = threadIdx.x;
    int b = blockIdx.x;       // class id

    // ---- Phase 1: partial mean/max over this block's 1000-elem fg slice ----
    {
        float psum = 0.f, pmax = -INFINITY;
        for (int j = t; j < 1000; j += TB) {
            int idx = b * 1000 + j;
            int r = idx / K_N;
            int c = idx - r * K_N;
            float v = __ldg(scores + r * NCLS_P1 + c);
            psum += v;
            pmax = fmaxf(pmax, v);
        }
        #pragma unroll
        for (int o = 16; o; o >>= 1) {
            psum += __shfl_xor_sync(0xffffffffu, psum, o);
            pmax = fmaxf(pmax, __shfl_xor_sync(0xffffffffu, pmax, o));
        }
        if ((t & 31) == 0) { wsum[t >> 5] = psum; wmax[t >> 5] = pmax; }
    }
    __syncthreads();
    if (t == 0) {
        float s = 0.f, m = -INFINITY;
        #pragma unroll
        for (int i = 0; i < TB / 32; i++) { s += wsum[i]; m = fmaxf(m, wmax[i]); }
        g_psum[b] = s; g_pmax[b] = m;
        __threadfence();
        atomicAdd(&g_bar1, 1);
    }

    // ---- prefetch this class's score column (overlaps the barrier wait) ----
    for (int r = t; r < R_N; r += TB)
        allscore[r] = __ldg(scores + r * NCLS_P1 + b);
    if (t == 0) {
        while (*(volatile int*)&g_bar1 < K_N) { }
        __threadfence();
        s_cnt = 0;
    }
    __syncthreads();

    // ---- Phase 2: fold 80 partials (identical tree in every block) ----
    if (t < 128) {
        rsum[t] = (t < K_N) ? g_psum[t] : 0.f;
        rmax[t] = (t < K_N) ? g_pmax[t] : -INFINITY;
    }
    __syncthreads();
    #pragma unroll
    for (int s = 64; s > 0; s >>= 1) {
        if (t < s) { rsum[t] += rsum[t + s]; rmax[t] = fmaxf(rmax[t], rmax[t + s]); }
        __syncthreads();
    }
    float th = fminf(0.05f, 0.5f * (rsum[0] / (float)(R_N * K_N) + rmax[0]));

    // ---- Phase 3a: compact valid candidates ----
    for (int r = t; r < R_N; r += TB) {
        float s = allscore[r];
        if (s > th) {
            int p = atomicAdd(&s_cnt, 1);
            cscore[p] = s;
            cidx[p] = r;
        }
    }
    __syncthreads();
    int V = s_cnt;

    // ---- Phase 3b: rank-counting sort + gather V clipped boxes ----
    for (int i = t; i < V; i += TB) {
        float si = cscore[i];
        int   ii = cidx[i];
        int rank = 0;
        for (int j = 0; j < V; j++) {
            float sj = cscore[j];
            rank += (sj > si) || (sj == si && cidx[j] < ii);
        }
        float4 bx = __ldg((const float4*)boxes + ii * K_N + b);
        float x1 = fminf(fmaxf(bx.x, 0.f), IMG_W_F);
        float y1 = fminf(fmaxf(bx.y, 0.f), IMG_H_F);
        float x2 = fminf(fmaxf(bx.z, 0.f), IMG_W_F);
        float y2 = fminf(fmaxf(bx.w, 0.f), IMG_H_F);
        sscore[rank] = si;
        sidx[rank]   = ii;
        sbx[rank]    = make_float4(x1, y1, x2, y2);
        sarea[rank]  = fmaxf(x2 - x1, 0.f) * fmaxf(y2 - y1, 0.f);
    }
    __syncthreads();

    // ---- Phase 3c: warp-register greedy NMS (warp 0, no block barriers) ----
    if (t < 32) {
        int lane = t;
        u64 removed = 0;                       // lane w owns bits [64w, 64w+64)
        int nk = 0;
        for (int i = 0; i < V; i++) {
            u64 wv = __shfl_sync(0xffffffffu, removed, i >> 6);
            if (!((wv >> (i & 63)) & 1ull)) {
                if (lane == 0) klist[nk] = i;
                nk++;
                if (nk >= CPC) break;
                float4 bi = sbx[i];
                float  ai = sarea[i];
                for (int jb = i + 1; jb < V; jb += 32) {
                    int j = jb + lane;
                    bool sup = false;
                    if (j < V) {
                        float4 bj = sbx[j];
                        float xx1 = fmaxf(bi.x, bj.x);
                        float yy1 = fmaxf(bi.y, bj.y);
                        float xx2 = fminf(bi.z, bj.z);
                        float yy2 = fminf(bi.w, bj.w);
                        float inter = fmaxf(xx2 - xx1, 0.f) * fmaxf(yy2 - yy1, 0.f);
                        float uni = fmaxf(ai + sarea[j] - inter, 1e-9f);
                        sup = inter > 0.5f * uni;
                    }
                    u32 bm = __ballot_sync(0xffffffffu, sup);
                    int w0 = jb >> 6, off0 = jb & 63;
                    if (lane == w0)     removed |= ((u64)bm) << off0;
                    if (lane == w0 + 1 && off0) removed |= ((u64)bm) >> (64 - off0);
                }
            }
        }
        if (lane == 0) s_nk = nk;
    }
    __syncthreads();

    // ---- Phase 3d: emit top-100 kept ----
    {
        int nk = s_nk;
        int base = b * CPC;
        if (t < CPC) {
            if (t < nk) {
                int i = klist[t];
                g_ord[base + t]  = ord32(sscore[i]);
                g_prop[base + t] = sidx[i];
            } else {
                g_ord[base + t]  = 0u;
                g_prop[base + t] = 0;
            }
        }
    }
    __syncthreads();

    // ---- grid barrier 2; only block 0 continues ----
    if (t == 0) { __threadfence(); atomicAdd(&g_bar2, 1); }
    if (b != 0) return;
    if (t == 0) {
        while (*(volatile int*)&g_bar2 < K_N) { }
        __threadfence();
        s_scount = 0;
    }
    __syncthreads();

    // ---- Phase 4: exact top-100 via 8-pass u64 byte-radix select ----
    u32* ordsh = (u32*)(smraw + OFF_ORDSH);
    u32* hist  = (u32*)(smraw + OFF_HIST);
    u64* surv  = (u64*)(smraw + OFF_SURV);
    u64* win   = (u64*)(smraw + OFF_WIN);

    for (int i = t; i < K_N * CPC; i += TB) ordsh[i] = g_ord[i];
    __syncthreads();

    u32 prefOrd = 0, ordMask = 0;
    u32 prefTb = 0,  tbMask = 0;
    int need = CPC;
    #pragma unroll 1
    for (int pass = 0; pass < 8; pass++) {
        bool ordPass = pass < 4;
        int shift = ordPass ? 8 * (3 - pass) : 8 * (7 - pass);
        if (t < 256) hist[t] = 0;
        __syncthreads();
        for (int i = t; i < K_N * CPC; i += TB) {
            u32 o = ordsh[i];
            u32 tb = tb_of(i);
            if (((o ^ prefOrd) & ordMask) == 0 && ((tb ^ prefTb) & tbMask) == 0) {
                u32 byte = ((ordPass ? o : tb) >> shift) & 255u;
                atomicAdd(&hist[byte], 1u);
            }
        }
        __syncthreads();
        // parallel bucket selection (warp 0): find v with
        // suffix_ex(v) < need <= suffix_ex(v) + hist[v], buckets descending
        if (t < 32) {
            int lane = t;
            u32 h8[8];
            int local = 0;
            #pragma unroll
            for (int q = 0; q < 8; q++) {
                h8[q] = hist[255 - 8 * lane - q];
                local += (int)h8[q];
            }
            int inc = local;                       // inclusive scan over lanes asc
            #pragma unroll
            for (int o = 1; o < 32; o <<= 1) {
                int v2 = __shfl_up_sync(0xffffffffu, inc, o);
                if (lane >= o) inc += v2;
            }
            int pre = inc - local;                 // suffix-exclusive for my first bucket
            if (pre < need && need <= inc) {
                int acc = pre;
                #pragma unroll
                for (int q = 0; q < 8; q++) {
                    int h = (int)h8[q];
                    if (acc + h >= need) { s_chosen = 255 - 8 * lane - q; s_need = need - acc; break; }
                    acc += h;
                }
            }
        }
        __syncthreads();
        u32 ch = (u32)s_chosen;
        need = s_need;
        if (ordPass) { prefOrd |= ch << shift; ordMask |= 255u << shift; }
        else         { prefTb  |= ch << shift; tbMask  |= 255u << shift; }
        __syncthreads();
    }
    u64 T64 = ((u64)prefOrd << 32) | prefTb;   // exact 100th-largest key

    // gather exactly the 100 keys >= T64 (keys unique)
    for (int i = t; i < K_N * CPC; i += TB) {
        u64 key = ((u64)ordsh[i] << 32) | tb_of(i);
        if (key >= T64) {
            int p = atomicAdd(&s_scount, 1);
            surv[p] = key;
        }
    }
    __syncthreads();
    int S = s_scount;   // == 100

    if (t < S) {
        u64 ki = surv[t];
        int r = 0;
        for (int j = 0; j < S; j++) r += (surv[j] > ki);
        win[r] = ki;
    }
    __syncthreads();

    // ---- Output: [100, 87] = box(4) | score | class | full_scores(81) ----
    for (int e = t; e < CPC * OUT_COLS; e += TB) {
        int row = e / OUT_COLS;
        int col = e - row * OUT_COLS;
        u64 key = win[row];
        u32 o = (u32)(key >> 32);
        float val = 0.f;
        if (o != 0u) {
            u32 low = (u32)key;
            int c = (K_N - 1) - (int)((low >> 7) & 127u);
            int k = (CPC - 1) - (int)(low & 127u);
            int prop = g_prop[c * CPC + k];
            if (col < 4) {
                float bv = __ldg(boxes + prop * (K_N * 4) + c * 4 + col);
                float lim = (col & 1) ? IMG_H_F : IMG_W_F;
                val = fminf(fmaxf(bv, 0.f), lim);
            } else if (col == 4) {
                val = __uint_as_float(o & 0x7FFFFFFFu);
            } else if (col == 5) {
                val = (float)c;
            } else {
                val = __ldg(scores + prop * NCLS_P1 + (col - 6));
            }
        }
        out[e] = val;
    }
    __syncthreads();
    if (t == 0) { g_bar1 = 0; g_bar2 = 0; }   // reset for next graph replay
}

// ---------------------------------------------------------------------------
extern "C" void kernel_launch(void* const* d_in, const int* in_sizes, int n_in,
                              void* d_out, int out_size) {
    const float* boxes  = (const float*)d_in[0];
    const float* scores = (const float*)d_in[1];
    if (in_sizes[0] != R_N * K_N * 4) {
        boxes  = (const float*)d_in[1];
        scores = (const float*)d_in[0];
    }
    cudaFuncSetAttribute(fused_kernel, cudaFuncAttributeMaxDynamicSharedMemorySize, DYN_SMEM);
    fused_kernel<<<K_N, TB, DYN_SMEM>>>(boxes, scores, (float*)d_out);
}

// round 7
// speedup vs baseline: 2.4560x; 1.6265x over previous
#include <cuda_runtime.h>
#include <math.h>
#include <stdint.h>

#define R_N 1000
#define K_N 80
#define NCLS_P1 81
#define IMG_W_F 1333.0f
#define IMG_H_F 800.0f
#define CPC 100
#define OUT_COLS 87
#define TB 512

typedef unsigned long long u64;
typedef unsigned int u32;

__device__ u64 g_isum = 0;                 // fixed-point sum (x 2^32)
__device__ u32 g_imax = 0;                 // ord32 of global fg max
__device__ u64 g_keys[K_N * CPC];          // compacted kept keys
__device__ int g_props[K_N * CPC];         // matching proposal rows
__device__ int g_total = 0;
__device__ int g_bar1 = 0;
__device__ int g_bar2 = 0;

__device__ __forceinline__ u32 ord32(float f) {
    u32 u = __float_as_uint(f);
    return (u & 0x80000000u) ? ~u : (u | 0x80000000u);
}

// ---- dynamic smem offsets: per-class phase layout ----
#define OFF_ALLSCORE 0        // float[1000]
#define OFF_CSCORE   4096     // float[1024]
#define OFF_CIDX     8192     // int[1024]
#define OFF_SSCORE   12288    // float[1024]
#define OFF_SIDX     16384    // int[1024]
#define OFF_SBX      20480    // float4[1024]
#define OFF_SAREA    36864    // float[1024]
#define OFF_KEEP     40960    // int[1024]   (fallback V>128 only)
#define OFF_ADJ      45056    // u32[128*4]  (adjacency bitmatrix)
// ---- block-0 tail layout (overlays the above) ----
#define OFF_SKEYS    0        // u64[8000]   64000 B
#define OFF_HIST     64000    // u32[256]
#define OFF_SURV     65024    // u64[128]
#define OFF_SPROP    66048    // int[128]
#define OFF_WIN      66560    // u64[128]
#define OFF_WPROP    67584    // int[128]
#define DYN_SMEM     68096

__global__ void __launch_bounds__(TB) fused_kernel(const float* __restrict__ boxes,
                                                   const float* __restrict__ scores,
                                                   float* __restrict__ out) {
    extern __shared__ char smraw[];
    float*  allscore = (float*)(smraw + OFF_ALLSCORE);
    float*  cscore   = (float*)(smraw + OFF_CSCORE);
    int*    cidx     = (int*)(smraw + OFF_CIDX);
    float*  sscore   = (float*)(smraw + OFF_SSCORE);
    int*    sidx     = (int*)(smraw + OFF_SIDX);
    float4* sbx      = (float4*)(smraw + OFF_SBX);
    float*  sarea    = (float*)(smraw + OFF_SAREA);
    int*    s_keep   = (int*)(smraw + OFF_KEEP);
    u32*    adjw     = (u32*)(smraw + OFF_ADJ);

    __shared__ float wsum[TB / 32], wmax[TB / 32];
    __shared__ u32 keepw[32];
    __shared__ int klist[CPC];
    __shared__ float s_th;
    __shared__ int s_cnt, s_nk, s_base, s_chosen, s_need, s_scount, s_n;

    int t = threadIdx.x;
    int b = blockIdx.x;       // class id

    // ================= Phase 1: column load + partial reduce =================
    float psum = 0.f, pmax = -INFINITY;
    for (int r = t; r < R_N; r += TB) {
        float v = __ldg(scores + r * NCLS_P1 + b);
        allscore[r] = v;
        psum += v;
        pmax = fmaxf(pmax, v);
    }
    #pragma unroll
    for (int o = 16; o; o >>= 1) {
        psum += __shfl_xor_sync(0xffffffffu, psum, o);
        pmax = fmaxf(pmax, __shfl_xor_sync(0xffffffffu, pmax, o));
    }
    if ((t & 31) == 0) { wsum[t >> 5] = psum; wmax[t >> 5] = pmax; }
    __syncthreads();

    if (t == 0) {
        float s = 0.f, m = -INFINITY;
        #pragma unroll
        for (int i = 0; i < TB / 32; i++) { s += wsum[i]; m = fmaxf(m, wmax[i]); }
        atomicAdd(&g_isum, (u64)(s * 4294967296.0f));
        atomicMax(&g_imax, ord32(m));
        __threadfence();
        atomicAdd(&g_bar1, 1);
        while (*(volatile int*)&g_bar1 < K_N) { }
        __threadfence();
        u64 isum = *(volatile u64*)&g_isum;
        u32 imax = *(volatile u32*)&g_imax;
        float mean = (float)isum * (1.0f / 4294967296.0f) / (float)(R_N * K_N);
        float mx = __uint_as_float(imax & 0x7FFFFFFFu);   // scores >= 0
        s_th = fminf(0.05f, 0.5f * (mean + mx));
        s_cnt = 0;
    }
    __syncthreads();
    float th = s_th;

    // ================= Phase 2: compact valid candidates =====================
    for (int r = t; r < R_N; r += TB) {
        float s = allscore[r];
        if (s > th) {
            int p = atomicAdd(&s_cnt, 1);
            cscore[p] = s;
            cidx[p] = r;
        }
    }
    __syncthreads();
    int V = s_cnt;

    // ================= Phase 3: rank sort + gather boxes =====================
    for (int i = t; i < V; i += TB) {
        float si = cscore[i];
        int   ii = cidx[i];
        int rank = 0;
        for (int j = 0; j < V; j++) {
            float sj = cscore[j];
            rank += (sj > si) || (sj == si && cidx[j] < ii);
        }
        float4 bx = __ldg((const float4*)boxes + ii * K_N + b);
        float x1 = fminf(fmaxf(bx.x, 0.f), IMG_W_F);
        float y1 = fminf(fmaxf(bx.y, 0.f), IMG_H_F);
        float x2 = fminf(fmaxf(bx.z, 0.f), IMG_W_F);
        float y2 = fminf(fmaxf(bx.w, 0.f), IMG_H_F);
        sscore[rank] = si;
        sidx[rank]   = ii;
        sbx[rank]    = make_float4(x1, y1, x2, y2);
        sarea[rank]  = fmaxf(x2 - x1, 0.f) * fmaxf(y2 - y1, 0.f);
    }
    __syncthreads();

    // ================= Phase 4: NMS ==========================================
    if (V <= 128) {
        // adjacency matrix (upper triangle), fully parallel
        for (int w = t; w < 4 * V; w += TB) adjw[w] = 0;
        __syncthreads();
        int tot = V * V;
        for (int p = t; p < tot; p += TB) {
            int i = p / V, j = p - i * V;
            if (j > i) {
                float4 bi = sbx[i], bj = sbx[j];
                float xx1 = fmaxf(bi.x, bj.x);
                float yy1 = fmaxf(bi.y, bj.y);
                float xx2 = fminf(bi.z, bj.z);
                float yy2 = fminf(bi.w, bj.w);
                float inter = fmaxf(xx2 - xx1, 0.f) * fmaxf(yy2 - yy1, 0.f);
                float uni = fmaxf(sarea[i] + sarea[j] - inter, 1e-9f);
                if (inter > 0.5f * uni)
                    atomicOr(&adjw[i * 4 + (j >> 5)], 1u << (j & 31));
            }
        }
        __syncthreads();
        // bit-parallel greedy closure (single thread, registers)
        if (t == 0) {
            u64 a0 = (V >= 64) ? ~0ull : ((1ull << V) - 1ull);
            u64 a1 = (V <= 64) ? 0ull : ((V >= 128) ? ~0ull : ((1ull << (V - 64)) - 1ull));
            for (int i = 0; i < V; i++) {
                u64 r0 = ((u64)adjw[i * 4 + 1] << 32) | adjw[i * 4 + 0];
                u64 r1 = ((u64)adjw[i * 4 + 3] << 32) | adjw[i * 4 + 2];
                u64 w = (i < 64) ? a0 : a1;
                if ((w >> (i & 63)) & 1ull) { a0 &= ~r0; a1 &= ~r1; }
            }
            keepw[0] = (u32)a0; keepw[1] = (u32)(a0 >> 32);
            keepw[2] = (u32)a1; keepw[3] = (u32)(a1 >> 32);
        }
        __syncthreads();
    } else {
        // generic fallback (never hit on bench shapes): serial block NMS
        for (int i = t; i < V; i += TB) s_keep[i] = 1;
        __syncthreads();
        for (int i = 0; i < V; i++) {
            if (s_keep[i]) {
                float4 bi = sbx[i];
                float  ai = sarea[i];
                for (int j = i + 1 + t; j < V; j += TB) {
                    if (s_keep[j]) {
                        float4 bj = sbx[j];
                        float xx1 = fmaxf(bi.x, bj.x);
                        float yy1 = fmaxf(bi.y, bj.y);
                        float xx2 = fminf(bi.z, bj.z);
                        float yy2 = fminf(bi.w, bj.w);
                        float inter = fmaxf(xx2 - xx1, 0.f) * fmaxf(yy2 - yy1, 0.f);
                        float uni = fmaxf(ai + sarea[j] - inter, 1e-9f);
                        if (inter > 0.5f * uni) s_keep[j] = 0;
                    }
                }
            }
            __syncthreads();
        }
        if (t < 32) {
            for (int s0 = 0; s0 < V; s0 += 32) {
                int j = s0 + t;
                u32 m = __ballot_sync(0xffffffffu, (j < V) ? s_keep[j] : 0);
                if (t == 0) keepw[s0 >> 5] = m;
            }
        }
        __syncthreads();
    }

    // ================= Phase 5: emit kept (<=100) to compacted global ========
    if (t < 32) {
        int nk = 0;
        for (int s0 = 0; s0 < V && nk < CPC; s0 += 32) {
            u32 m = keepw[s0 >> 5];
            int kp = (m >> t) & 1;
            int myr = nk + __popc(m & ((1u << t) - 1u));
            if (kp && myr < CPC) klist[myr] = s0 + t;
            nk += __popc(m);
        }
        if (t == 0) s_nk = (nk < CPC) ? nk : CPC;
    }
    __syncthreads();
    if (t == 0) s_base = atomicAdd(&g_total, s_nk);
    __syncthreads();
    if (t < s_nk) {
        int i = klist[t];
        u32 o = ord32(sscore[i]);
        // key low-32: strictly decreasing in flat (c,k) => ties break like top_k
        u64 key = ((u64)o << 32) | (u32)(((K_N - 1 - b) << 7) | (CPC - 1 - t));
        g_keys[s_base + t]  = key;
        g_props[s_base + t] = sidx[i];
    }
    __syncthreads();
    if (t == 0) { __threadfence(); atomicAdd(&g_bar2, 1); }
    if (b != 0) return;

    // ================= Phase 6 (block 0): global top-100 =====================
    if (t == 0) {
        while (*(volatile int*)&g_bar2 < K_N) { }
        __threadfence();
        s_n = *(volatile int*)&g_total;
        s_scount = 0;
    }
    __syncthreads();
    int n = s_n;

    u64* skeys = (u64*)(smraw + OFF_SKEYS);
    u32* hist  = (u32*)(smraw + OFF_HIST);
    u64* surv  = (u64*)(smraw + OFF_SURV);
    int* sprop = (int*)(smraw + OFF_SPROP);
    u64* win   = (u64*)(smraw + OFF_WIN);
    int* wprop = (int*)(smraw + OFF_WPROP);

    for (int i = t; i < n; i += TB) skeys[i] = __ldcg(&g_keys[i]);
    if (t < 128) { win[t] = 0; wprop[t] = 0; }
    __syncthreads();

    u64 T64 = 1;             // n <= 100: every real key (ord>0) survives
    if (n > CPC) {
        u64 pref = 0, mask = 0;
        int need = CPC;
        #pragma unroll 1
        for (int pass = 0; pass < 8; pass++) {
            int shift = 8 * (7 - pass);
            if (t < 256) hist[t] = 0;
            __syncthreads();
            for (int i = t; i < n; i += TB) {
                u64 kk = skeys[i];
                if ((kk & mask) == pref)
                    atomicAdd(&hist[(u32)(kk >> shift) & 255u], 1u);
            }
            __syncthreads();
            if (t < 32) {                     // warp-parallel bucket select
                int lane = t;
                u32 h8[8]; int local = 0;
                #pragma unroll
                for (int q = 0; q < 8; q++) { h8[q] = hist[255 - 8 * lane - q]; local += (int)h8[q]; }
                int inc = local;
                #pragma unroll
                for (int o = 1; o < 32; o <<= 1) {
                    int v2 = __shfl_up_sync(0xffffffffu, inc, o);
                    if (lane >= o) inc += v2;
                }
                int pre = inc - local;
                if (pre < need && need <= inc) {
                    int acc = pre;
                    #pragma unroll
                    for (int q = 0; q < 8; q++) {
                        int h = (int)h8[q];
                        if (acc + h >= need) { s_chosen = 255 - 8 * lane - q; s_need = need - acc; break; }
                        acc += h;
                    }
                }
            }
            __syncthreads();
            pref |= ((u64)(u32)s_chosen) << shift;
            mask |= 255ull << shift;
            need = s_need;
            __syncthreads();
        }
        T64 = pref;          // exact 100th-largest key (keys unique)
    }

    for (int i = t; i < n; i += TB) {
        u64 kk = skeys[i];
        if (kk >= T64) {
            int p = atomicAdd(&s_scount, 1);
            surv[p]  = kk;
            sprop[p] = __ldcg(&g_props[i]);
        }
    }
    __syncthreads();
    int S = s_scount;        // == min(n, 100)

    if (t < S) {
        u64 kk = surv[t];
        int r = 0;
        for (int j = 0; j < S; j++) r += (surv[j] > kk);
        win[r] = kk;
        wprop[r] = sprop[t];
    }
    __syncthreads();

    // ---- Output: [100, 87] = box(4) | score | class | full_scores(81) ----
    for (int e = t; e < CPC * OUT_COLS; e += TB) {
        int row = e / OUT_COLS;
        int col = e - row * OUT_COLS;
        u64 key = win[row];
        u32 o = (u32)(key >> 32);
        float val = 0.f;
        if (o != 0u) {
            int c = (K_N - 1) - (int)(((u32)key >> 7) & 127u);
            int prop = wprop[row];
            if (col < 4) {
                float bv = __ldg(boxes + prop * (K_N * 4) + c * 4 + col);
                float lim = (col & 1) ? IMG_H_F : IMG_W_F;
                val = fminf(fmaxf(bv, 0.f), lim);
            } else if (col == 4) {
                val = __uint_as_float(o & 0x7FFFFFFFu);
            } else if (col == 5) {
                val = (float)c;
            } else {
                val = __ldg(scores + prop * NCLS_P1 + (col - 6));
            }
        }
        out[e] = val;
    }
    __syncthreads();
    if (t == 0) {            // reset globals for next graph replay
        g_bar1 = 0; g_bar2 = 0; g_total = 0;
        g_isum = 0; g_imax = 0;
    }
}

// ---------------------------------------------------------------------------
extern "C" void kernel_launch(void* const* d_in, const int* in_sizes, int n_in,
                              void* d_out, int out_size) {
    const float* boxes  = (const float*)d_in[0];
    const float* scores = (const float*)d_in[1];
    if (in_sizes[0] != R_N * K_N * 4) {
        boxes  = (const float*)d_in[1];
        scores = (const float*)d_in[0];
    }
    cudaFuncSetAttribute(fused_kernel, cudaFuncAttributeMaxDynamicSharedMemorySize, DYN_SMEM);
    fused_kernel<<<K_N, TB, DYN_SMEM>>>(boxes, scores, (float*)d_out);
}

// round 8
// speedup vs baseline: 3.1946x; 1.3007x over previous
#include <cuda_runtime.h>
#include <math.h>
#include <stdint.h>

#define R_N 1000
#define K_N 80
#define NCLS_P1 81
#define IMG_W_F 1333.0f
#define IMG_H_F 800.0f
#define CPC 100
#define OUT_COLS 87
#define TB 1024
#define SURV_CAP 512

typedef unsigned long long u64;
typedef unsigned int u32;

__device__ u64 g_isum = 0;                 // fixed-point sum (x 2^32)
__device__ u32 g_imax = 0;                 // ord32 of global fg max
__device__ u64 g_keys[K_N * CPC];          // compacted kept keys
__device__ int g_props[K_N * CPC];         // matching proposal rows
__device__ int g_total = 0;
__device__ int g_bar1 = 0;
__device__ int g_bar2 = 0;

__device__ __forceinline__ u32 ord32(float f) {
    u32 u = __float_as_uint(f);
    return (u & 0x80000000u) ? ~u : (u | 0x80000000u);
}

// ---- dynamic smem offsets: per-class phase layout ----
#define OFF_ALLSCORE 0        // float[1000]
#define OFF_CSCORE   4096     // float[1024]
#define OFF_CIDX     8192     // int[1024]
#define OFF_SSCORE   12288    // float[1024]
#define OFF_SIDX     16384    // int[1024]
#define OFF_SBX      20480    // float4[1024]
#define OFF_SAREA    36864    // float[1024]
#define OFF_KEEP     40960    // int[1024]   (fallback V>128 only)
#define OFF_ADJ      45056    // u32[128*4]
// ---- tail layout (last-arriving block, overlays the above) ----
#define OFF_SKEYS    0        // u64[8000]  64000
#define OFF_HIST     64000    // u32[256]
#define OFF_SURV     65024    // u64[512]
#define OFF_SPROP    69120    // int[512]
#define OFF_WIN      71168    // u64[128]
#define OFF_WPROP    72192    // int[128]
#define DYN_SMEM     73728

__global__ void __launch_bounds__(TB) fused_kernel(const float* __restrict__ boxes,
                                                   const float* __restrict__ scores,
                                                   float* __restrict__ out) {
    extern __shared__ char smraw[];
    float*  allscore = (float*)(smraw + OFF_ALLSCORE);
    float*  cscore   = (float*)(smraw + OFF_CSCORE);
    int*    cidx     = (int*)(smraw + OFF_CIDX);
    float*  sscore   = (float*)(smraw + OFF_SSCORE);
    int*    sidx     = (int*)(smraw + OFF_SIDX);
    float4* sbx      = (float4*)(smraw + OFF_SBX);
    float*  sarea    = (float*)(smraw + OFF_SAREA);
    int*    s_keep   = (int*)(smraw + OFF_KEEP);
    u32*    adjw     = (u32*)(smraw + OFF_ADJ);

    __shared__ float wsum[TB / 32], wmax[TB / 32];
    __shared__ u32 keepw[32];
    __shared__ int klist[CPC];
    __shared__ float s_th;
    __shared__ int s_cnt, s_nk, s_base, s_chosen, s_need, s_scount, s_n;
    __shared__ int s_last, s_spred;

    int t = threadIdx.x;
    int b = blockIdx.x;       // class id

    // ================= Phase 1: column load + partial reduce =================
    float psum = 0.f, pmax = -INFINITY;
    for (int r = t; r < R_N; r += TB) {
        float v = __ldg(scores + r * NCLS_P1 + b);
        allscore[r] = v;
        psum += v;
        pmax = fmaxf(pmax, v);
    }
    #pragma unroll
    for (int o = 16; o; o >>= 1) {
        psum += __shfl_xor_sync(0xffffffffu, psum, o);
        pmax = fmaxf(pmax, __shfl_xor_sync(0xffffffffu, pmax, o));
    }
    if ((t & 31) == 0) { wsum[t >> 5] = psum; wmax[t >> 5] = pmax; }
    __syncthreads();
    if (t == 0) {
        float s = 0.f, m = -INFINITY;
        #pragma unroll
        for (int i = 0; i < TB / 32; i++) { s += wsum[i]; m = fmaxf(m, wmax[i]); }
        atomicAdd(&g_isum, (u64)(s * 4294967296.0f));
        atomicMax(&g_imax, ord32(m));
        __threadfence();
        atomicAdd(&g_bar1, 1);     // arrive only; wait deferred (speculation)
    }

    // ========== Phases 2-4, speculative (th = 0.05) with verify/redo =========
    float th_cur = 0.05f;
    int V = 0;
    for (int attempt = 0; ; attempt++) {
        if (t == 0) s_cnt = 0;
        __syncthreads();
        // compact
        for (int r = t; r < R_N; r += TB) {
            float s = allscore[r];
            if (s > th_cur) {
                int p = atomicAdd(&s_cnt, 1);
                cscore[p] = s;
                cidx[p] = r;
            }
        }
        __syncthreads();
        V = s_cnt;

        // rank-counting sort (score desc, idx asc) + gather clipped boxes
        for (int i = t; i < V; i += TB) {
            float si = cscore[i];
            int   ii = cidx[i];
            int rank = 0;
            for (int j = 0; j < V; j++) {
                float sj = cscore[j];
                rank += (sj > si) || (sj == si && cidx[j] < ii);
            }
            float4 bx = __ldg((const float4*)boxes + ii * K_N + b);
            float x1 = fminf(fmaxf(bx.x, 0.f), IMG_W_F);
            float y1 = fminf(fmaxf(bx.y, 0.f), IMG_H_F);
            float x2 = fminf(fmaxf(bx.z, 0.f), IMG_W_F);
            float y2 = fminf(fmaxf(bx.w, 0.f), IMG_H_F);
            sscore[rank] = si;
            sidx[rank]   = ii;
            sbx[rank]    = make_float4(x1, y1, x2, y2);
            sarea[rank]  = fmaxf(x2 - x1, 0.f) * fmaxf(y2 - y1, 0.f);
        }
        __syncthreads();

        // NMS
        if (V <= 128) {
            for (int w = t; w < 4 * V; w += TB) adjw[w] = 0;
            __syncthreads();
            int tot = V * V;
            for (int p = t; p < tot; p += TB) {
                int i = p / V, j = p - i * V;
                if (j > i) {
                    float4 bi = sbx[i], bj = sbx[j];
                    float xx1 = fmaxf(bi.x, bj.x);
                    float yy1 = fmaxf(bi.y, bj.y);
                    float xx2 = fminf(bi.z, bj.z);
                    float yy2 = fminf(bi.w, bj.w);
                    float inter = fmaxf(xx2 - xx1, 0.f) * fmaxf(yy2 - yy1, 0.f);
                    float uni = fmaxf(sarea[i] + sarea[j] - inter, 1e-9f);
                    if (inter > 0.5f * uni)
                        atomicOr(&adjw[i * 4 + (j >> 5)], 1u << (j & 31));
                }
            }
            __syncthreads();
            if (t == 0) {            // bit-parallel greedy closure
                u64 a0 = (V >= 64) ? ~0ull : ((1ull << V) - 1ull);
                u64 a1 = (V <= 64) ? 0ull : ((V >= 128) ? ~0ull : ((1ull << (V - 64)) - 1ull));
                for (int i = 0; i < V; i++) {
                    u64 r0 = ((u64)adjw[i * 4 + 1] << 32) | adjw[i * 4 + 0];
                    u64 r1 = ((u64)adjw[i * 4 + 3] << 32) | adjw[i * 4 + 2];
                    u64 w = (i < 64) ? a0 : a1;
                    if ((w >> (i & 63)) & 1ull) { a0 &= ~r0; a1 &= ~r1; }
                }
                keepw[0] = (u32)a0; keepw[1] = (u32)(a0 >> 32);
                keepw[2] = (u32)a1; keepw[3] = (u32)(a1 >> 32);
            }
            __syncthreads();
        } else {
            // generic fallback: serial block NMS
            for (int i = t; i < V; i += TB) s_keep[i] = 1;
            __syncthreads();
            for (int i = 0; i < V; i++) {
                if (s_keep[i]) {
                    float4 bi = sbx[i];
                    float  ai = sarea[i];
                    for (int j = i + 1 + t; j < V; j += TB) {
                        if (s_keep[j]) {
                            float4 bj = sbx[j];
                            float xx1 = fmaxf(bi.x, bj.x);
                            float yy1 = fmaxf(bi.y, bj.y);
                            float xx2 = fminf(bi.z, bj.z);
                            float yy2 = fminf(bi.w, bj.w);
                            float inter = fmaxf(xx2 - xx1, 0.f) * fmaxf(yy2 - yy1, 0.f);
                            float uni = fmaxf(ai + sarea[j] - inter, 1e-9f);
                            if (inter > 0.5f * uni) s_keep[j] = 0;
                        }
                    }
                }
                __syncthreads();
            }
            if (t < 32) {
                for (int s0 = 0; s0 < V; s0 += 32) {
                    int j = s0 + t;
                    u32 m = __ballot_sync(0xffffffffu, (j < V) ? s_keep[j] : 0);
                    if (t == 0) keepw[s0 >> 5] = m;
                }
            }
            __syncthreads();
        }

        if (attempt > 0) break;
        // verify the speculation against the true threshold
        if (t == 0) {
            while (*(volatile int*)&g_bar1 < K_N) { }
            __threadfence();
            u64 isum = *(volatile u64*)&g_isum;
            u32 imax = *(volatile u32*)&g_imax;
            float mean = (float)isum * (1.0f / 4294967296.0f) / (float)(R_N * K_N);
            float mx = __uint_as_float(imax & 0x7FFFFFFFu);   // scores >= 0
            s_th = fminf(0.05f, 0.5f * (mean + mx));
        }
        __syncthreads();
        if (s_th == th_cur) break;    // speculation exact (common case)
        th_cur = s_th;                // rare: redo with true threshold
    }

    // ============== Phase 5: emit kept (<=100) to compacted global ===========
    if (t < 32) {
        int nk = 0;
        for (int s0 = 0; s0 < V && nk < CPC; s0 += 32) {
            u32 m = keepw[s0 >> 5];
            int kp = (m >> t) & 1;
            int myr = nk + __popc(m & ((1u << t) - 1u));
            if (kp && myr < CPC) klist[myr] = s0 + t;
            nk += __popc(m);
        }
        if (t == 0) s_nk = (nk < CPC) ? nk : CPC;
    }
    __syncthreads();
    if (t == 0) s_base = atomicAdd(&g_total, s_nk);
    __syncthreads();
    if (t < s_nk) {
        int i = klist[t];
        u32 o = ord32(sscore[i]);
        // low-32 strictly decreasing in flat (c,k) => ties break like top_k
        u64 key = ((u64)o << 32) | (u32)(((K_N - 1 - b) << 7) | (CPC - 1 - t));
        g_keys[s_base + t]  = key;
        g_props[s_base + t] = sidx[i];
    }
    __syncthreads();

    // ============ grid barrier 2: LAST arriver runs the tail =================
    if (t == 0) {
        __threadfence();
        int old = atomicAdd(&g_bar2, 1);
        s_last = (old == K_N - 1);
        if (s_last) {
            __threadfence();
            s_n = *(volatile int*)&g_total;
            s_scount = 0;
        }
    }
    __syncthreads();
    if (!s_last) return;
    int n = s_n;

    // ================= Tail: global top-100 ==================================
    u64* skeys = (u64*)(smraw + OFF_SKEYS);
    u32* hist  = (u32*)(smraw + OFF_HIST);
    u64* surv  = (u64*)(smraw + OFF_SURV);
    int* sprop = (int*)(smraw + OFF_SPROP);
    u64* win   = (u64*)(smraw + OFF_WIN);
    int* wprop = (int*)(smraw + OFF_WPROP);

    for (int i = t; i < n; i += TB) skeys[i] = __ldcg(&g_keys[i]);
    if (t < 128) { win[t] = 0; wprop[t] = 0; }
    __syncthreads();

    u64 pref = 0;
    if (n > CPC) {
        u64 mask = 0;
        int need = CPC;
        int done = 0;
        #pragma unroll 1
        for (int pass = 0; pass < 8 && !done; pass++) {
            int shift = 8 * (7 - pass);
            if (t < 256) hist[t] = 0;
            __syncthreads();
            for (int i = t; i < n; i += TB) {
                u64 kk = skeys[i];
                if ((kk & mask) == pref)
                    atomicAdd(&hist[(u32)(kk >> shift) & 255u], 1u);
            }
            __syncthreads();
            if (t < 32) {                     // warp-parallel bucket select
                int lane = t;
                u32 h8[8]; int local = 0;
                #pragma unroll
                for (int q = 0; q < 8; q++) { h8[q] = hist[255 - 8 * lane - q]; local += (int)h8[q]; }
                int inc = local;
                #pragma unroll
                for (int o = 1; o < 32; o <<= 1) {
                    int v2 = __shfl_up_sync(0xffffffffu, inc, o);
                    if (lane >= o) inc += v2;
                }
                int pre = inc - local;
                if (pre < need && need <= inc) {
                    int acc = pre;
                    #pragma unroll
                    for (int q = 0; q < 8; q++) {
                        int h = (int)h8[q];
                        if (acc + h >= need) { s_chosen = 255 - 8 * lane - q; s_need = need - acc; break; }
                        acc += h;
                    }
                }
            }
            __syncthreads();
            if (pass == 3 && t == 0)          // survivors if we stop at ord-32
                s_spred = (CPC - s_need) + (int)hist[s_chosen];
            pref |= ((u64)(u32)s_chosen) << shift;
            mask |= 255ull << shift;
            need = s_need;
            __syncthreads();
            if (pass == 3 && s_spred <= SURV_CAP) done = 1;   // uniform branch
        }
        // gather predicate: key >= pref (low bytes of pref are 0 when done at
        // pass 3 => selects ord >= T_ord; after 8 passes selects exactly 100)
    }

    for (int i = t; i < n; i += TB) {
        u64 kk = skeys[i];
        if (kk >= pref || n <= CPC) {
            int p = atomicAdd(&s_scount, 1);
            if (p < SURV_CAP) { surv[p] = kk; sprop[p] = __ldcg(&g_props[i]); }
        }
    }
    __syncthreads();
    int S = s_scount;
    if (S > SURV_CAP) S = SURV_CAP;

    // rank survivors by full key (unique); keep top 100
    if (t < S) {
        u64 kk = surv[t];
        int r = 0;
        for (int j = 0; j < S; j++) r += (surv[j] > kk);
        if (r < CPC) { win[r] = kk; wprop[r] = sprop[t]; }
    }
    __syncthreads();

    // ---- Output: [100, 87] = box(4) | score | class | full_scores(81) ----
    for (int e = t; e < CPC * OUT_COLS; e += TB) {
        int row = e / OUT_COLS;
        int col = e - row * OUT_COLS;
        u64 key = win[row];
        u32 o = (u32)(key >> 32);
        float val = 0.f;
        if (o != 0u) {
            int c = (K_N - 1) - (int)(((u32)key >> 7) & 127u);
            int prop = wprop[row];
            if (col < 4) {
                float bv = __ldg(boxes + prop * (K_N * 4) + c * 4 + col);
                float lim = (col & 1) ? IMG_H_F : IMG_W_F;
                val = fminf(fmaxf(bv, 0.f), lim);
            } else if (col == 4) {
                val = __uint_as_float(o & 0x7FFFFFFFu);
            } else if (col == 5) {
                val = (float)c;
            } else {
                val = __ldg(scores + prop * NCLS_P1 + (col - 6));
            }
        }
        out[e] = val;
    }
    __syncthreads();
    if (t == 0) {            // reset globals for next graph replay
        g_bar1 = 0; g_bar2 = 0; g_total = 0;
        g_isum = 0; g_imax = 0;
    }
}

// ---------------------------------------------------------------------------
extern "C" void kernel_launch(void* const* d_in, const int* in_sizes, int n_in,
                              void* d_out, int out_size) {
    const float* boxes  = (const float*)d_in[0];
    const float* scores = (const float*)d_in[1];
    if (in_sizes[0] != R_N * K_N * 4) {
        boxes  = (const float*)d_in[1];
        scores = (const float*)d_in[0];
    }
    cudaFuncSetAttribute(fused_kernel, cudaFuncAttributeMaxDynamicSharedMemorySize, DYN_SMEM);
    fused_kernel<<<K_N, TB, DYN_SMEM>>>(boxes, scores, (float*)d_out);
}

// round 9
// speedup vs baseline: 3.4554x; 1.0816x over previous
#include <cuda_runtime.h>
#include <math.h>
#include <stdint.h>

#define R_N 1000
#define K_N 80
#define NCLS_P1 81
#define IMG_W_F 1333.0f
#define IMG_H_F 800.0f
#define CPC 100
#define OUT_COLS 87
#define TB 1024
#define SURV_CAP 512

typedef unsigned long long u64;
typedef unsigned int u32;

__device__ u64 g_isum = 0;                 // fixed-point sum (x 2^32)
__device__ u32 g_imax = 0;                 // ord32 of global fg max
__device__ u64 g_keys[K_N * CPC];          // compacted kept keys
__device__ int g_props[K_N * CPC];         // matching proposal rows
__device__ int g_total = 0;
__device__ int g_bar1 = 0;
__device__ int g_bar2 = 0;

__device__ __forceinline__ u32 ord32(float f) {
    u32 u = __float_as_uint(f);
    return (u & 0x80000000u) ? ~u : (u | 0x80000000u);
}

// ---- dynamic smem offsets: per-class phase layout ----
#define OFF_ALLSCORE 0        // float[1000]
#define OFF_CSCORE   4096     // float[1024]
#define OFF_CIDX     8192     // int[1024]
#define OFF_SSCORE   12288    // float[1024]
#define OFF_SIDX     16384    // int[1024]
#define OFF_SBX      20480    // float4[1024]
#define OFF_SAREA    36864    // float[1024]
#define OFF_KEEP     40960    // int[1024]   (fallback V>128 only)
#define OFF_ADJ      45056    // u32[128*4]
// ---- tail layout (last-arriving block, overlays the above) ----
#define OFF_SKEYS    0        // u64[8000]  64000
#define OFF_HIST     64000    // u32[256]
#define OFF_SURV     65024    // u64[512]
#define OFF_SPROP    69120    // int[512]
#define OFF_WIN      71168    // u64[128]
#define OFF_WPROP    72192    // int[128]
#define DYN_SMEM     73728

__global__ void __launch_bounds__(TB) fused_kernel(const float* __restrict__ boxes,
                                                   const float* __restrict__ scores,
                                                   float* __restrict__ out) {
    extern __shared__ char smraw[];
    float*  allscore = (float*)(smraw + OFF_ALLSCORE);
    float*  cscore   = (float*)(smraw + OFF_CSCORE);
    int*    cidx     = (int*)(smraw + OFF_CIDX);
    float*  sscore   = (float*)(smraw + OFF_SSCORE);
    int*    sidx     = (int*)(smraw + OFF_SIDX);
    float4* sbx      = (float4*)(smraw + OFF_SBX);
    float*  sarea    = (float*)(smraw + OFF_SAREA);
    int*    s_keep   = (int*)(smraw + OFF_KEEP);
    u32*    adjw     = (u32*)(smraw + OFF_ADJ);

    __shared__ float wsum[TB / 32], wmax[TB / 32];
    __shared__ u32 keepw[32];
    __shared__ int klist[CPC];
    __shared__ float s_th;
    __shared__ int s_cnt, s_nk, s_base, s_chosen, s_need, s_scount, s_n;
    __shared__ int s_last, s_spred;

    int t = threadIdx.x;
    int b = blockIdx.x;       // class id

    // ==== Phase 1: column load + partial reduce + SPECULATIVE compact =======
    if (t == 0) s_cnt = 0;
    __syncthreads();
    float psum = 0.f, pmax = -INFINITY;
    for (int r = t; r < R_N; r += TB) {
        float v = __ldg(scores + r * NCLS_P1 + b);
        allscore[r] = v;
        psum += v;
        pmax = fmaxf(pmax, v);
        if (v > 0.05f) {                       // speculation: th == 0.05f
            int p = atomicAdd(&s_cnt, 1);
            cscore[p] = v;
            cidx[p] = r;
        }
    }
    #pragma unroll
    for (int o = 16; o; o >>= 1) {
        psum += __shfl_xor_sync(0xffffffffu, psum, o);
        pmax = fmaxf(pmax, __shfl_xor_sync(0xffffffffu, pmax, o));
    }
    if ((t & 31) == 0) { wsum[t >> 5] = psum; wmax[t >> 5] = pmax; }
    __syncthreads();
    if (t == 0) {
        float s = 0.f, m = -INFINITY;
        #pragma unroll
        for (int i = 0; i < TB / 32; i++) { s += wsum[i]; m = fmaxf(m, wmax[i]); }
        atomicAdd(&g_isum, (u64)(s * 4294967296.0f));
        atomicMax(&g_imax, ord32(m));
        __threadfence();
        atomicAdd(&g_bar1, 1);     // arrive only; verification deferred
    }

    // ========== Phases 2-4: sort + NMS (speculative, verify/redo) ============
    float th_cur = 0.05f;
    int V = 0;
    for (int attempt = 0; ; attempt++) {
        if (attempt > 0) {                     // rare: recompact with true th
            if (t == 0) s_cnt = 0;
            __syncthreads();
            for (int r = t; r < R_N; r += TB) {
                float s = allscore[r];
                if (s > th_cur) {
                    int p = atomicAdd(&s_cnt, 1);
                    cscore[p] = s;
                    cidx[p] = r;
                }
            }
        }
        __syncthreads();
        V = s_cnt;

        // rank-counting sort (score desc, idx asc) + gather clipped boxes
        for (int i = t; i < V; i += TB) {
            float si = cscore[i];
            int   ii = cidx[i];
            int rank = 0;
            for (int j = 0; j < V; j++) {
                float sj = cscore[j];
                rank += (sj > si) || (sj == si && cidx[j] < ii);
            }
            float4 bx = __ldg((const float4*)boxes + ii * K_N + b);
            float x1 = fminf(fmaxf(bx.x, 0.f), IMG_W_F);
            float y1 = fminf(fmaxf(bx.y, 0.f), IMG_H_F);
            float x2 = fminf(fmaxf(bx.z, 0.f), IMG_W_F);
            float y2 = fminf(fmaxf(bx.w, 0.f), IMG_H_F);
            sscore[rank] = si;
            sidx[rank]   = ii;
            sbx[rank]    = make_float4(x1, y1, x2, y2);
            sarea[rank]  = fmaxf(x2 - x1, 0.f) * fmaxf(y2 - y1, 0.f);
        }
        __syncthreads();

        // NMS
        if (V <= 128) {
            for (int w = t; w < 4 * V; w += TB) adjw[w] = 0;
            __syncthreads();
            int tot = V * V;
            for (int p = t; p < tot; p += TB) {
                int i = p / V, j = p - i * V;
                if (j > i) {
                    float4 bi = sbx[i], bj = sbx[j];
                    float xx1 = fmaxf(bi.x, bj.x);
                    float yy1 = fmaxf(bi.y, bj.y);
                    float xx2 = fminf(bi.z, bj.z);
                    float yy2 = fminf(bi.w, bj.w);
                    float inter = fmaxf(xx2 - xx1, 0.f) * fmaxf(yy2 - yy1, 0.f);
                    float uni = fmaxf(sarea[i] + sarea[j] - inter, 1e-9f);
                    if (inter > 0.5f * uni)
                        atomicOr(&adjw[i * 4 + (j >> 5)], 1u << (j & 31));
                }
            }
            __syncthreads();
            if (t == 0) {            // bit-parallel greedy closure
                u64 a0 = (V >= 64) ? ~0ull : ((1ull << V) - 1ull);
                u64 a1 = (V <= 64) ? 0ull : ((V >= 128) ? ~0ull : ((1ull << (V - 64)) - 1ull));
                for (int i = 0; i < V; i++) {
                    u64 r0 = ((u64)adjw[i * 4 + 1] << 32) | adjw[i * 4 + 0];
                    u64 r1 = ((u64)adjw[i * 4 + 3] << 32) | adjw[i * 4 + 2];
                    u64 w = (i < 64) ? a0 : a1;
                    if ((w >> (i & 63)) & 1ull) { a0 &= ~r0; a1 &= ~r1; }
                }
                keepw[0] = (u32)a0; keepw[1] = (u32)(a0 >> 32);
                keepw[2] = (u32)a1; keepw[3] = (u32)(a1 >> 32);
            }
            __syncthreads();
        } else {
            // generic fallback: serial block NMS
            for (int i = t; i < V; i += TB) s_keep[i] = 1;
            __syncthreads();
            for (int i = 0; i < V; i++) {
                if (s_keep[i]) {
                    float4 bi = sbx[i];
                    float  ai = sarea[i];
                    for (int j = i + 1 + t; j < V; j += TB) {
                        if (s_keep[j]) {
                            float4 bj = sbx[j];
                            float xx1 = fmaxf(bi.x, bj.x);
                            float yy1 = fmaxf(bi.y, bj.y);
                            float xx2 = fminf(bi.z, bj.z);
                            float yy2 = fminf(bi.w, bj.w);
                            float inter = fmaxf(xx2 - xx1, 0.f) * fmaxf(yy2 - yy1, 0.f);
                            float uni = fmaxf(ai + sarea[j] - inter, 1e-9f);
                            if (inter > 0.5f * uni) s_keep[j] = 0;
                        }
                    }
                }
                __syncthreads();
            }
            if (t < 32) {
                for (int s0 = 0; s0 < V; s0 += 32) {
                    int j = s0 + t;
                    u32 m = __ballot_sync(0xffffffffu, (j < V) ? s_keep[j] : 0);
                    if (t == 0) keepw[s0 >> 5] = m;
                }
            }
            __syncthreads();
        }

        if (attempt > 0) break;
        // verify speculation against the true threshold
        if (t == 0) {
            while (*(volatile int*)&g_bar1 < K_N) { }
            __threadfence();
            u64 isum = *(volatile u64*)&g_isum;
            u32 imax = *(volatile u32*)&g_imax;
            float mean = (float)isum * (1.0f / 4294967296.0f) / (float)(R_N * K_N);
            float mx = __uint_as_float(imax & 0x7FFFFFFFu);   // scores >= 0
            s_th = fminf(0.05f, 0.5f * (mean + mx));
        }
        __syncthreads();
        if (s_th == th_cur) break;    // speculation exact (common case)
        th_cur = s_th;                // rare: redo with true threshold
    }

    // ============== Phase 5: emit kept (<=100) to compacted global ===========
    if (t < 32) {
        int nk = 0;
        for (int s0 = 0; s0 < V && nk < CPC; s0 += 32) {
            u32 m = keepw[s0 >> 5];
            int kp = (m >> t) & 1;
            int myr = nk + __popc(m & ((1u << t) - 1u));
            if (kp && myr < CPC) klist[myr] = s0 + t;
            nk += __popc(m);
        }
        if (t == 0) s_nk = (nk < CPC) ? nk : CPC;
    }
    __syncthreads();
    if (t == 0) s_base = atomicAdd(&g_total, s_nk);
    __syncthreads();
    if (t < s_nk) {
        int i = klist[t];
        u32 o = ord32(sscore[i]);
        // low-32 strictly decreasing in flat (c,k) => ties break like top_k
        u64 key = ((u64)o << 32) | (u32)(((K_N - 1 - b) << 7) | (CPC - 1 - t));
        g_keys[s_base + t]  = key;
        g_props[s_base + t] = sidx[i];
    }
    __syncthreads();

    // ============ grid barrier 2: LAST arriver runs the tail =================
    if (t == 0) {
        __threadfence();
        int old = atomicAdd(&g_bar2, 1);
        s_last = (old == K_N - 1);
        if (s_last) {
            __threadfence();
            s_n = *(volatile int*)&g_total;
            s_scount = 0;
        }
    }
    __syncthreads();
    if (!s_last) return;
    int n = s_n;

    // ================= Tail: global top-100 ==================================
    u64* skeys = (u64*)(smraw + OFF_SKEYS);
    u32* hist  = (u32*)(smraw + OFF_HIST);
    u64* surv  = (u64*)(smraw + OFF_SURV);
    int* sprop = (int*)(smraw + OFF_SPROP);
    u64* win   = (u64*)(smraw + OFF_WIN);
    int* wprop = (int*)(smraw + OFF_WPROP);

    for (int i = t; i < n; i += TB) skeys[i] = __ldcg(&g_keys[i]);
    if (t < 128) { win[t] = 0; wprop[t] = 0; }
    __syncthreads();

    u64 pref = 0;
    if (n > CPC) {
        u64 mask = 0;
        int need = CPC;
        int done = 0;
        #pragma unroll 1
        for (int pass = 0; pass < 8 && !done; pass++) {
            int shift = 8 * (7 - pass);
            if (t < 256) hist[t] = 0;
            __syncthreads();
            for (int i = t; i < n; i += TB) {
                u64 kk = skeys[i];
                if ((kk & mask) == pref)
                    atomicAdd(&hist[(u32)(kk >> shift) & 255u], 1u);
            }
            __syncthreads();
            if (t < 32) {                     // warp-parallel bucket select
                int lane = t;
                u32 h8[8]; int local = 0;
                #pragma unroll
                for (int q = 0; q < 8; q++) { h8[q] = hist[255 - 8 * lane - q]; local += (int)h8[q]; }
                int inc = local;
                #pragma unroll
                for (int o = 1; o < 32; o <<= 1) {
                    int v2 = __shfl_up_sync(0xffffffffu, inc, o);
                    if (lane >= o) inc += v2;
                }
                int pre = inc - local;
                if (pre < need && need <= inc) {
                    int acc = pre;
                    #pragma unroll
                    for (int q = 0; q < 8; q++) {
                        int h = (int)h8[q];
                        if (acc + h >= need) { s_chosen = 255 - 8 * lane - q; s_need = need - acc; break; }
                        acc += h;
                    }
                }
            }
            __syncthreads();
            // survivors if we stop after this pass = (CPC - need_new) + hist[chosen]
            if (t == 0) s_spred = (CPC - s_need) + (int)hist[s_chosen];
            pref |= ((u64)(u32)s_chosen) << shift;
            mask |= 255ull << shift;
            need = s_need;
            __syncthreads();
            if (s_spred <= SURV_CAP) done = 1;   // uniform early exit
        }
        // gather predicate key >= pref: trailing zero bytes => full chosen
        // bucket + everything above; exact top-100 resolved by the rank below
    }

    for (int i = t; i < n; i += TB) {
        u64 kk = skeys[i];
        if (kk >= pref || n <= CPC) {
            int p = atomicAdd(&s_scount, 1);
            if (p < SURV_CAP) { surv[p] = kk; sprop[p] = __ldcg(&g_props[i]); }
        }
    }
    __syncthreads();
    int S = s_scount;
    if (S > SURV_CAP) S = SURV_CAP;

    // rank survivors by full key (unique); keep top 100
    if (t < S) {
        u64 kk = surv[t];
        int r = 0;
        for (int j = 0; j < S; j++) r += (surv[j] > kk);
        if (r < CPC) { win[r] = kk; wprop[r] = sprop[t]; }
    }
    __syncthreads();

    // ---- Output: [100, 87] = box(4) | score | class | full_scores(81) ----
    for (int e = t; e < CPC * OUT_COLS; e += TB) {
        int row = e / OUT_COLS;
        int col = e - row * OUT_COLS;
        u64 key = win[row];
        u32 o = (u32)(key >> 32);
        float val = 0.f;
        if (o != 0u) {
            int c = (K_N - 1) - (int)(((u32)key >> 7) & 127u);
            int prop = wprop[row];
            if (col < 4) {
                float bv = __ldg(boxes + prop * (K_N * 4) + c * 4 + col);
                float lim = (col & 1) ? IMG_H_F : IMG_W_F;
                val = fminf(fmaxf(bv, 0.f), lim);
            } else if (col == 4) {
                val = __uint_as_float(o & 0x7FFFFFFFu);
            } else if (col == 5) {
                val = (float)c;
            } else {
                val = __ldg(scores + prop * NCLS_P1 + (col - 6));
            }
        }
        out[e] = val;
    }
    __syncthreads();
    if (t == 0) {            // reset globals for next graph replay
        g_bar1 = 0; g_bar2 = 0; g_total = 0;
        g_isum = 0; g_imax = 0;
    }
}

// ---------------------------------------------------------------------------
extern "C" void kernel_launch(void* const* d_in, const int* in_sizes, int n_in,
                              void* d_out, int out_size) {
    const float* boxes  = (const float*)d_in[0];
    const float* scores = (const float*)d_in[1];
    if (in_sizes[0] != R_N * K_N * 4) {
        boxes  = (const float*)d_in[1];
        scores = (const float*)d_in[0];
    }
    cudaFuncSetAttribute(fused_kernel, cudaFuncAttributeMaxDynamicSharedMemorySize, DYN_SMEM);
    fused_kernel<<<K_N, TB, DYN_SMEM>>>(boxes, scores, (float*)d_out);
}